// round 4
// baseline (speedup 1.0000x reference)
#include <cuda_runtime.h>
#include <cuda_bf16.h>
#include <cstdint>

#define T 8
#define V 10000
#define E 100000
#define C_IN 128
#define H 256
#define DS 16
#define C_OUT 64
#define HD (H * DS)  // 4096
#define TV (T * V)   // 80000

// ---------------------------------------------------------------------------
// Scratch (device globals; no allocation allowed)
// ---------------------------------------------------------------------------
__device__ __align__(128) float g_x0[(size_t)TV * C_IN];
__device__ __align__(128) float g_x1[(size_t)TV * H];
__device__ __align__(128) float g_hT[(size_t)H * TV];    // h transposed [hh][t][v]
__device__ __align__(128) float g_xsr[(size_t)TV * H];
__device__ __align__(128) float g_agg[(size_t)TV * H];
__device__ __align__(128) float g_deg[(size_t)TV];
__device__ __align__(128) float g_lam[2 * HD];
__device__ __align__(128) float g_xlast[(size_t)V * H];
__device__ __align__(128) float g_xsrl [(size_t)V * H];
__device__ int g_is64;

// bf16 hi/lo split, transposed weights ([N=256][K], K-major)
__device__ __align__(128) __nv_bfloat16 g_cat0_h[256 * 256], g_cat0_l[256 * 256];
__device__ __align__(128) __nv_bfloat16 g_cat1_h[256 * 512], g_cat1_l[256 * 512];
__device__ __align__(128) __nv_bfloat16 g_res0_h[256 * 128], g_res0_l[256 * 128];
__device__ __align__(128) __nv_bfloat16 g_res1_h[256 * 256], g_res1_l[256 * 256];
__device__ __align__(128) __nv_bfloat16 g_mix0_h[256 * HD],  g_mix0_l[256 * HD];
__device__ __align__(128) __nv_bfloat16 g_mix1_h[256 * HD],  g_mix1_l[256 * HD];

// ---------------------------------------------------------------------------
// Helpers
// ---------------------------------------------------------------------------
__device__ __forceinline__ uint32_t smem_u32(const void* p) {
    uint32_t a;
    asm("{ .reg .u64 t; cvta.to.shared.u64 t, %1; cvt.u32.u64 %0, t; }" : "=r"(a) : "l"(p));
    return a;
}

__device__ __forceinline__ void bf_split(float x, __nv_bfloat16& h_, __nv_bfloat16& l_) {
    h_ = __float2bfloat16(x);
    l_ = __float2bfloat16(x - __bfloat162float(h_));
}

#define LDSM_X4(r0, r1, r2, r3, addr) \
    asm volatile("ldmatrix.sync.aligned.m8n8.x4.shared.b16 {%0,%1,%2,%3}, [%4];" \
        : "=r"(r0), "=r"(r1), "=r"(r2), "=r"(r3) : "r"(addr))

#define MMA_BF16(d, a, b0, b1) \
    asm volatile("mma.sync.aligned.m16n8k16.row.col.f32.bf16.bf16.f32 " \
        "{%0,%1,%2,%3}, {%4,%5,%6,%7}, {%8,%9}, {%0,%1,%2,%3};" \
        : "+f"((d)[0]), "+f"((d)[1]), "+f"((d)[2]), "+f"((d)[3]) \
        : "r"((a)[0]), "r"((a)[1]), "r"((a)[2]), "r"((a)[3]), "r"(b0), "r"(b1))

#define CP16(dst, src) \
    asm volatile("cp.async.cg.shared.global [%0], [%1], 16;" :: "r"(dst), "l"(src))
#define CP_COMMIT() asm volatile("cp.async.commit_group;" ::: "memory")
#define CP_WAIT0()  asm volatile("cp.async.wait_group 0;" ::: "memory")

// ---------------------------------------------------------------------------
// Small kernels
// ---------------------------------------------------------------------------
__global__ void zero_kernel(float4* p, long long n4) {
    long long i = blockIdx.x * (long long)blockDim.x + threadIdx.x;
    long long stride = (long long)gridDim.x * blockDim.x;
    for (; i < n4; i += stride) p[i] = make_float4(0.f, 0.f, 0.f, 0.f);
}

__global__ void detect_kernel(const unsigned int* ei) {
    if (threadIdx.x == 0 && blockIdx.x == 0) {
        unsigned int s = 0;
        for (int i = 0; i < 64; i++) s |= ei[2 * i + 1];
        g_is64 = (s == 0) ? 1 : 0;
    }
}

__device__ __forceinline__ int load_edge(const void* ei, long long pos) {
    if (g_is64) return (int)((const long long*)ei)[pos];
    return ((const int*)ei)[pos];
}

__global__ void lam_kernel(const float* a0, const float* a1, float* lam) {
    int i = blockIdx.x * blockDim.x + threadIdx.x;
    if (i < HD)           lam[i] = expf(-expf(a0[i]));
    else if (i < 2 * HD)  lam[i] = expf(-expf(a1[i - HD]));
}

__global__ void token_mix_kernel(const float* __restrict__ xs,
                                 const float* __restrict__ w,
                                 const float* __restrict__ b,
                                 float* __restrict__ out) {
    int idx = blockIdx.x * blockDim.x + threadIdx.x;
    if (idx >= TV * C_IN) return;
    int c = idx % C_IN;
    int t = idx / (V * C_IN);
    float acc = b[c] + xs[idx] * w[c * 3 + 1];
    if (t > 0)     acc += xs[idx - V * C_IN] * w[c * 3 + 0];
    if (t < T - 1) acc += xs[idx + V * C_IN] * w[c * 3 + 2];
    out[idx] = acc;
}

__global__ void deg_kernel(const void* __restrict__ ei, float* __restrict__ deg) {
    long long i = blockIdx.x * (long long)blockDim.x + threadIdx.x;
    if (i >= (long long)T * E) return;
    int e = (int)(i % E);
    int t = (int)(i / E);
    int dst = load_edge(ei, (long long)t * 2 * E + E + e);
    atomicAdd(&deg[(long long)t * V + dst], 1.0f);
}

__global__ void scatter_kernel(const float* __restrict__ x, const void* __restrict__ ei,
                               float* __restrict__ agg, int C) {
    int chunks = C >> 2;
    long long idx = blockIdx.x * (long long)blockDim.x + threadIdx.x;
    long long total = (long long)T * E * chunks;
    if (idx >= total) return;
    int c4 = (int)(idx % chunks);
    long long te = idx / chunks;
    int e = (int)(te % E);
    int t = (int)(te / E);
    long long base = (long long)t * 2 * E;
    int src = load_edge(ei, base + e);
    int dst = load_edge(ei, base + E + e);
    float4 v = *(const float4*)&x[((long long)t * V + src) * C + c4 * 4];
    float* p = &agg[((long long)t * V + dst) * C + c4 * 4];
    asm volatile("red.global.add.v4.f32 [%0], {%1,%2,%3,%4};"
                 :: "l"(p), "f"(v.x), "f"(v.y), "f"(v.z), "f"(v.w) : "memory");
}

__global__ void mean_kernel(float* __restrict__ agg, const float* __restrict__ deg, int C) {
    int chunks = C >> 2;
    long long idx = blockIdx.x * (long long)blockDim.x + threadIdx.x;
    long long total = (long long)TV * chunks;
    if (idx >= total) return;
    long long row = idx / chunks;
    int c4 = (int)(idx % chunks);
    float inv = 1.0f / fmaxf(deg[row], 1.0f);
    float4* p = (float4*)&agg[row * C + c4 * 4];
    float4 v = *p;
    v.x *= inv; v.y *= inv; v.z *= inv; v.w *= inv;
    *p = v;
}

// Build transposed, bf16-split weights: dst[n][k] (K-major) from w1/w2 [K][256]
__global__ void bsplit_kernel(const float* __restrict__ w1, const float* __restrict__ w2,
                              int K1, int Kt,
                              __nv_bfloat16* __restrict__ hi, __nv_bfloat16* __restrict__ lo) {
    long long idx = blockIdx.x * (long long)blockDim.x + threadIdx.x;
    if (idx >= (long long)Kt * 256) return;
    int k = (int)(idx % Kt);
    int n = (int)(idx / Kt);
    float v = (k < K1) ? w1[(long long)k * 256 + n] : w2[(long long)(k - K1) * 256 + n];
    __nv_bfloat16 h_, l_;
    bf_split(v, h_, l_);
    hi[(long long)n * Kt + k] = h_;
    lo[(long long)n * Kt + k] = l_;
}

// ---------------------------------------------------------------------------
// Unified bf16x3 mma.sync GEMM with in-producer A generation.
//   MODE 0 (scan): A[r, k] = relu( Horner_{τ<tsteps}( lam[k], B[k], hT[k>>4, τ, r] ) )
//   MODE 1 (cat):  A[r, k] = concat(A1, A2)[r, k]  (fp32 -> bf16 hi/lo split)
// C[M,256] = (Ah+Al) @ (Bh+Bl)^T + bias (+ Dadd). Optional transposed C write.
// Tile 64x256, K chunks of 32, 256 threads (8 warps: 2m x 4n, warp tile 32x64).
// B operand streamed with cp.async; double-buffered SMEM.
// ---------------------------------------------------------------------------
#define ROWB 80
#define A_T  5120            // 64 * 80
#define B_T  20480           // 256 * 80
#define STG  (2 * A_T + 2 * B_T)   // 51200
#define GSMEM (2 * STG)            // 102400

template <int MODE>
__global__ __launch_bounds__(256) void mgemm_kernel(
    const float* __restrict__ A1, const float* __restrict__ A2, int K1,
    const float* __restrict__ hT, const float* __restrict__ lam,
    const float* __restrict__ Bp, int tsteps,
    const __nv_bfloat16* __restrict__ Bh, const __nv_bfloat16* __restrict__ Bl,
    const float* __restrict__ bias, const float* __restrict__ Dadd,
    float* __restrict__ Cout, int M, int K, int trans_out)
{
    extern __shared__ char smem[];
    const uint32_t sb = smem_u32(smem);
    const int tid = threadIdx.x;
    const int wid = tid >> 5;
    const int lane = tid & 31;
    const int warp_m = wid >> 2;       // 0..1
    const int warp_n = wid & 3;        // 0..3
    const long long m0 = (long long)blockIdx.x * 64;

    // producer mapping: q = k-octet (0..3), r = row (0..63)
    const int q = tid >> 6;
    const int r = tid & 63;
    const long long rg = m0 + r;
    const bool rowok = (rg < M);

    float acc[2][8][4];
#pragma unroll
    for (int i = 0; i < 2; i++)
#pragma unroll
        for (int j = 0; j < 8; j++)
#pragma unroll
            for (int p = 0; p < 4; p++) acc[i][j][p] = 0.f;

    const int nK = K / 32;

    // prefetch registers
    float hx[8];
    float llam[8], bb[8];
    float a8[8];

    // ldmatrix base byte offsets within a stage
    const uint32_t aoff = (uint32_t)(warp_m * 32 + (lane & 15)) * ROWB +
                          (uint32_t)((lane >> 4) << 3) * 2;
    const uint32_t boff = (uint32_t)(warp_n * 64 + ((lane >> 4) << 3) + (lane & 7)) * ROWB +
                          (uint32_t)(((lane >> 3) & 1) << 3) * 2;

    auto prefetchA = [&](int kt) {
        const int kg = kt * 32 + q * 8;
        if (MODE == 0) {
            *(float4*)&llam[0] = *(const float4*)&lam[kg];
            *(float4*)&llam[4] = *(const float4*)&lam[kg + 4];
            *(float4*)&bb[0]   = *(const float4*)&Bp[kg];
            *(float4*)&bb[4]   = *(const float4*)&Bp[kg + 4];
            const long long hb = (long long)(kg >> 4) * TV + rg;
#pragma unroll
            for (int tt = 0; tt < 8; tt++)
                hx[tt] = (rowok && tt < tsteps) ? hT[hb + (long long)tt * V] : 0.f;
        } else {
            if (rowok) {
                const float* src = (kg < K1) ? &A1[rg * K1 + kg]
                                             : &A2[rg * (K - K1) + (kg - K1)];
                *(float4*)&a8[0] = ((const float4*)src)[0];
                *(float4*)&a8[4] = ((const float4*)src)[1];
            } else {
#pragma unroll
                for (int d = 0; d < 8; d++) a8[d] = 0.f;
            }
        }
    };

    auto produceA = [&](int stage) {
        float s[8];
        if (MODE == 0) {
#pragma unroll
            for (int d = 0; d < 8; d++) s[d] = 0.f;
#pragma unroll
            for (int tt = 0; tt < 8; tt++) {
                if (tt < tsteps) {
                    float x = hx[tt];
#pragma unroll
                    for (int d = 0; d < 8; d++) s[d] = llam[d] * s[d] + x * bb[d];
                }
            }
#pragma unroll
            for (int d = 0; d < 8; d++) s[d] = fmaxf(s[d], 0.f);
        } else {
#pragma unroll
            for (int d = 0; d < 8; d++) s[d] = a8[d];
        }
        uint32_t uh[4], ul[4];
#pragma unroll
        for (int d2 = 0; d2 < 4; d2++) {
            __nv_bfloat16 h0, l0, h1, l1;
            bf_split(s[d2 * 2 + 0], h0, l0);
            bf_split(s[d2 * 2 + 1], h1, l1);
            uh[d2] = (uint32_t)__bfloat16_as_ushort(h0) |
                     ((uint32_t)__bfloat16_as_ushort(h1) << 16);
            ul[d2] = (uint32_t)__bfloat16_as_ushort(l0) |
                     ((uint32_t)__bfloat16_as_ushort(l1) << 16);
        }
        const uint32_t off = (uint32_t)stage * STG + (uint32_t)r * ROWB + (uint32_t)q * 16;
        *(uint4*)(smem + off)       = make_uint4(uh[0], uh[1], uh[2], uh[3]);
        *(uint4*)(smem + off + A_T) = make_uint4(ul[0], ul[1], ul[2], ul[3]);
    };

    auto cpB = [&](int kt, int stage) {
        const int k0 = kt * 32;
        const uint32_t base = sb + stage * STG + 2 * A_T;
#pragma unroll
        for (int i = 0; i < 4; i++) {
            int idx = tid + 256 * i;
            int n = idx >> 2;
            int kq = idx & 3;
            uint32_t dst = base + (uint32_t)n * ROWB + (uint32_t)kq * 16;
            long long soff = (long long)n * K + k0 + kq * 8;
            CP16(dst, Bh + soff);
            CP16(dst + B_T, Bl + soff);
        }
    };

    auto compute = [&](int stage) {
        const uint32_t base = sb + stage * STG;
#pragma unroll
        for (int ks = 0; ks < 2; ks++) {
            const uint32_t kk = (uint32_t)ks * 32;   // 16 k-elems = 32 bytes
            uint32_t a_h[2][4], a_l[2][4];
#pragma unroll
            for (int i = 0; i < 2; i++) {
                uint32_t ad = base + aoff + (uint32_t)(i * 16) * ROWB + kk;
                LDSM_X4(a_h[i][0], a_h[i][1], a_h[i][2], a_h[i][3], ad);
                LDSM_X4(a_l[i][0], a_l[i][1], a_l[i][2], a_l[i][3], ad + A_T);
            }
            uint32_t b_h[16], b_l[16];
#pragma unroll
            for (int jj = 0; jj < 4; jj++) {
                uint32_t bd = base + 2 * A_T + boff + (uint32_t)(jj * 16) * ROWB + kk;
                LDSM_X4(b_h[jj * 4 + 0], b_h[jj * 4 + 1], b_h[jj * 4 + 2], b_h[jj * 4 + 3], bd);
                LDSM_X4(b_l[jj * 4 + 0], b_l[jj * 4 + 1], b_l[jj * 4 + 2], b_l[jj * 4 + 3], bd + B_T);
            }
#pragma unroll
            for (int i = 0; i < 2; i++)
#pragma unroll
                for (int j = 0; j < 8; j++) {
                    MMA_BF16(acc[i][j], a_h[i], b_h[j * 2], b_h[j * 2 + 1]);
                    MMA_BF16(acc[i][j], a_h[i], b_l[j * 2], b_l[j * 2 + 1]);
                    MMA_BF16(acc[i][j], a_l[i], b_h[j * 2], b_h[j * 2 + 1]);
                }
        }
    };

    // prologue: fill stage 0
    prefetchA(0);
    cpB(0, 0);
    CP_COMMIT();
    produceA(0);
    CP_WAIT0();
    __syncthreads();

    for (int kt = 0; kt < nK; kt++) {
        const int cur = kt & 1;
        const bool more = (kt + 1 < nK);
        if (more) {
            prefetchA(kt + 1);
            cpB(kt + 1, cur ^ 1);
            CP_COMMIT();
        }
        compute(cur);
        if (more) produceA(cur ^ 1);
        CP_WAIT0();
        __syncthreads();
    }

    // epilogue
#pragma unroll
    for (int i = 0; i < 2; i++) {
        long long r1 = m0 + warp_m * 32 + i * 16 + (lane >> 2);
        long long r2 = r1 + 8;
#pragma unroll
        for (int j = 0; j < 8; j++) {
            int c = warp_n * 64 + j * 8 + (lane & 3) * 2;
            float bx = 0.f, by = 0.f;
            if (bias) { float2 b2 = *(const float2*)&bias[c]; bx = b2.x; by = b2.y; }
            if (r1 < M) {
                float vx = acc[i][j][0] + bx, vy = acc[i][j][1] + by;
                if (Dadd) { float2 d = *(const float2*)&Dadd[r1 * 256 + c]; vx += d.x; vy += d.y; }
                if (trans_out) {
                    Cout[(long long)c * M + r1]       = vx;
                    Cout[(long long)(c + 1) * M + r1] = vy;
                } else {
                    *(float2*)&Cout[r1 * 256 + c] = make_float2(vx, vy);
                }
            }
            if (r2 < M) {
                float vx = acc[i][j][2] + bx, vy = acc[i][j][3] + by;
                if (Dadd) { float2 d = *(const float2*)&Dadd[r2 * 256 + c]; vx += d.x; vy += d.y; }
                if (trans_out) {
                    Cout[(long long)c * M + r2]       = vx;
                    Cout[(long long)(c + 1) * M + r2] = vy;
                } else {
                    *(float2*)&Cout[r2 * 256 + c] = make_float2(vx, vy);
                }
            }
        }
    }
}

// ---------------------------------------------------------------------------
// fp32 SGEMM for the small output head (N=64)
// ---------------------------------------------------------------------------
#define BMH 128
#define BNH 128
#define BKH 8

__global__ __launch_bounds__(256) void sgemm_kernel(
    const float* __restrict__ A, const float* __restrict__ B,
    const float* __restrict__ bias, float* __restrict__ C, int M, int N, int K)
{
    __shared__ float As[BKH][BMH];
    __shared__ float Bs[BKH][BNH];
    int row0 = blockIdx.y * BMH;
    int col0 = blockIdx.x * BNH;
    int tid = threadIdx.x;
    int aRow = tid >> 1;
    int aCol = (tid & 1) * 4;
    int bRow = tid >> 5;
    int bCol = (tid & 31) * 4;
    int tx = tid & 15;
    int ty = tid >> 4;
    float acc[8][8];
#pragma unroll
    for (int i = 0; i < 8; i++)
#pragma unroll
        for (int j = 0; j < 8; j++) acc[i][j] = 0.f;
    int nK = K / BKH;
    for (int kt = 0; kt < nK; ++kt) {
        int k0 = kt * BKH;
        float4 av = make_float4(0.f, 0.f, 0.f, 0.f);
        int gr = row0 + aRow;
        if (gr < M) av = *(const float4*)&A[(long long)gr * K + k0 + aCol];
        As[aCol + 0][aRow] = av.x;
        As[aCol + 1][aRow] = av.y;
        As[aCol + 2][aRow] = av.z;
        As[aCol + 3][aRow] = av.w;
        float4 bv = make_float4(0.f, 0.f, 0.f, 0.f);
        int gc = col0 + bCol;
        if (gc < N) bv = *(const float4*)&B[(long long)(k0 + bRow) * N + gc];
        *(float4*)&Bs[bRow][bCol] = bv;
        __syncthreads();
#pragma unroll
        for (int k = 0; k < BKH; k++) {
            float ar[8], br[8];
#pragma unroll
            for (int i = 0; i < 8; i++) ar[i] = As[k][ty * 8 + i];
#pragma unroll
            for (int j = 0; j < 8; j++) br[j] = Bs[k][tx * 8 + j];
#pragma unroll
            for (int i = 0; i < 8; i++)
#pragma unroll
                for (int j = 0; j < 8; j++) acc[i][j] += ar[i] * br[j];
        }
        __syncthreads();
    }
#pragma unroll
    for (int i = 0; i < 8; i++) {
        int r = row0 + ty * 8 + i;
        if (r >= M) continue;
#pragma unroll
        for (int j = 0; j < 8; j++) {
            int c = col0 + tx * 8 + j;
            if (c >= N) continue;
            C[(long long)r * N + c] = acc[i][j] + bias[c];
        }
    }
}

// ---------------------------------------------------------------------------
// Host helpers
// ---------------------------------------------------------------------------
static void zero_buf(float* p, long long n_floats) {
    zero_kernel<<<1024, 256>>>((float4*)p, n_floats / 4);
}

// MODE 1: C = concat(A1,A2) @ W + bias
static void mgemm_cat(const float* A1, const float* A2, int K1,
                      const __nv_bfloat16* Bh, const __nv_bfloat16* Bl,
                      const float* bias, const float* Dadd, float* C,
                      int M, int K, int trans_out) {
    int grid = (M + 63) / 64;
    mgemm_kernel<1><<<grid, 256, GSMEM>>>(A1, A2, K1, nullptr, nullptr, nullptr, 0,
                                          Bh, Bl, bias, Dadd, C, M, K, trans_out);
}

// MODE 0: C = relu(scan(hT; lam, Bp; tsteps)) @ W + bias + Dadd
static void mgemm_scan(const float* hT, const float* lam, const float* Bp, int tsteps,
                       const __nv_bfloat16* Bh, const __nv_bfloat16* Bl,
                       const float* bias, const float* Dadd, float* C, int M, int K) {
    int grid = (M + 63) / 64;
    mgemm_kernel<0><<<grid, 256, GSMEM>>>(nullptr, nullptr, 0, hT, lam, Bp, tsteps,
                                          Bh, Bl, bias, Dadd, C, M, K, 0);
}

// ---------------------------------------------------------------------------
// Launch
// ---------------------------------------------------------------------------
extern "C" void kernel_launch(void* const* d_in, const int* in_sizes, int n_in,
                              void* d_out, int out_size) {
    const float* xs      = (const float*)d_in[0];
    const void*  ei      = d_in[1];
    const float* w_pre   = (const float*)d_in[2];
    const float* b_pre   = (const float*)d_in[3];

    const float* w_res0  = (const float*)d_in[4];
    const float* b_res0  = (const float*)d_in[5];
    const float* w_self0 = (const float*)d_in[6];
    const float* w_neigh0= (const float*)d_in[7];
    const float* b_sage0 = (const float*)d_in[8];
    const float* a_log0  = (const float*)d_in[9];
    const float* B0      = (const float*)d_in[10];
    const float* w_mix0  = (const float*)d_in[11];
    const float* b_mix0  = (const float*)d_in[12];

    const float* w_res1  = (const float*)d_in[13];
    const float* b_res1  = (const float*)d_in[14];
    const float* w_self1 = (const float*)d_in[15];
    const float* w_neigh1= (const float*)d_in[16];
    const float* b_sage1 = (const float*)d_in[17];
    const float* a_log1  = (const float*)d_in[18];
    const float* B1      = (const float*)d_in[19];
    const float* w_mix1  = (const float*)d_in[20];
    const float* b_mix1  = (const float*)d_in[21];

    const float* w_out   = (const float*)d_in[22];
    const float* b_out   = (const float*)d_in[23];

    float *x0, *x1, *hT, *xsr, *agg, *deg, *lam, *xlast, *xsrl;
    cudaGetSymbolAddress((void**)&x0,    g_x0);
    cudaGetSymbolAddress((void**)&x1,    g_x1);
    cudaGetSymbolAddress((void**)&hT,    g_hT);
    cudaGetSymbolAddress((void**)&xsr,   g_xsr);
    cudaGetSymbolAddress((void**)&agg,   g_agg);
    cudaGetSymbolAddress((void**)&deg,   g_deg);
    cudaGetSymbolAddress((void**)&lam,   g_lam);
    cudaGetSymbolAddress((void**)&xlast, g_xlast);
    cudaGetSymbolAddress((void**)&xsrl,  g_xsrl);

    __nv_bfloat16 *cat0h, *cat0l, *cat1h, *cat1l, *res0h, *res0l, *res1h, *res1l;
    __nv_bfloat16 *mix0h, *mix0l, *mix1h, *mix1l;
    cudaGetSymbolAddress((void**)&cat0h, g_cat0_h);
    cudaGetSymbolAddress((void**)&cat0l, g_cat0_l);
    cudaGetSymbolAddress((void**)&cat1h, g_cat1_h);
    cudaGetSymbolAddress((void**)&cat1l, g_cat1_l);
    cudaGetSymbolAddress((void**)&res0h, g_res0_h);
    cudaGetSymbolAddress((void**)&res0l, g_res0_l);
    cudaGetSymbolAddress((void**)&res1h, g_res1_h);
    cudaGetSymbolAddress((void**)&res1l, g_res1_l);
    cudaGetSymbolAddress((void**)&mix0h, g_mix0_h);
    cudaGetSymbolAddress((void**)&mix0l, g_mix0_l);
    cudaGetSymbolAddress((void**)&mix1h, g_mix1_h);
    cudaGetSymbolAddress((void**)&mix1l, g_mix1_l);

    cudaFuncSetAttribute(mgemm_kernel<0>,
                         cudaFuncAttributeMaxDynamicSharedMemorySize, GSMEM);
    cudaFuncSetAttribute(mgemm_kernel<1>,
                         cudaFuncAttributeMaxDynamicSharedMemorySize, GSMEM);

    detect_kernel<<<1, 32>>>((const unsigned int*)ei);
    lam_kernel<<<(2 * HD + 255) / 256, 256>>>(a_log0, a_log1, lam);
    token_mix_kernel<<<(TV * C_IN + 255) / 256, 256>>>(xs, w_pre, b_pre, x0);

    // weight preprocessing (transpose + bf16 hi/lo split)
    {
        auto bs = [](const float* w1, const float* w2, int K1, int Kt,
                     __nv_bfloat16* hi, __nv_bfloat16* lo) {
            long long tot = (long long)Kt * 256;
            bsplit_kernel<<<(int)((tot + 255) / 256), 256>>>(w1, w2, K1, Kt, hi, lo);
        };
        bs(w_self0, w_neigh0, C_IN, 2 * C_IN, cat0h, cat0l);
        bs(w_self1, w_neigh1, H, 2 * H, cat1h, cat1l);
        bs(w_res0, nullptr, C_IN, C_IN, res0h, res0l);
        bs(w_res1, nullptr, H, H, res1h, res1l);
        bs(w_mix0, nullptr, HD, HD, mix0h, mix0l);
        bs(w_mix1, nullptr, HD, HD, mix1h, mix1l);
    }

    // degrees (shared by both layers)
    zero_buf(deg, (long long)TV);
    deg_kernel<<<(int)(((long long)T * E + 255) / 256), 256>>>(ei, deg);

    // ---------------- layer 0 ----------------
    zero_buf(agg, (long long)TV * C_IN);
    {
        long long tot = (long long)T * E * (C_IN / 4);
        scatter_kernel<<<(int)((tot + 255) / 256), 256>>>(x0, ei, agg, C_IN);
        long long tm = (long long)TV * (C_IN / 4);
        mean_kernel<<<(int)((tm + 255) / 256), 256>>>(agg, deg, C_IN);
    }
    // sage0 -> hT (transposed write), res0 -> xsr
    mgemm_cat(x0, agg, C_IN, cat0h, cat0l, b_sage0, nullptr, hT, TV, 2 * C_IN, 1);
    mgemm_cat(x0, x0, C_IN, res0h, res0l, b_res0, nullptr, xsr, TV, C_IN, 0);

    // mix0 steps: scan recomputed in producer from hT
    for (int t = 0; t < T; t++) {
        mgemm_scan(hT, lam, B0, t + 1, mix0h, mix0l, b_mix0,
                   xsr + (long long)t * V * H, x1 + (long long)t * V * H, V, HD);
    }

    // ---------------- layer 1 ----------------
    zero_buf(agg, (long long)TV * H);
    {
        long long tot = (long long)T * E * (H / 4);
        scatter_kernel<<<(int)((tot + 255) / 256), 256>>>(x1, ei, agg, H);
        long long tm = (long long)TV * (H / 4);
        mean_kernel<<<(int)((tm + 255) / 256), 256>>>(agg, deg, H);
    }
    // sage1 -> hT (overwrites layer-0 hT; layer-0 consumers already done)
    mgemm_cat(x1, agg, H, cat1h, cat1l, b_sage1, nullptr, hT, TV, 2 * H, 1);
    // res1 at t = T-1 only
    mgemm_cat(x1 + (long long)(T - 1) * V * H, x1 + (long long)(T - 1) * V * H, H,
              res1h, res1l, b_res1, nullptr, xsrl, V, H, 0);
    // mix1 at t = T-1 only (full 8-step scan in producer)
    mgemm_scan(hT, lam + HD, B1, T, mix1h, mix1l, b_mix1, xsrl, xlast, V, HD);

    // ---------------- output head ----------------
    dim3 og((C_OUT + BNH - 1) / BNH, (V + BMH - 1) / BMH);
    sgemm_kernel<<<og, 256>>>(xlast, w_out, b_out, (float*)d_out, V, C_OUT, H);
}

// round 5
// speedup vs baseline: 1.8096x; 1.8096x over previous
#include <cuda_runtime.h>
#include <cuda_bf16.h>
#include <cstdint>

#define T 8
#define V 10000
#define VP 10048             // V padded to tile multiple (64)
#define E 100000
#define C_IN 128
#define H 256
#define DS 16
#define C_OUT 64
#define HD (H * DS)          // 4096
#define TV (T * V)           // 80000
#define ZST ((long long)VP * HD)

// ---------------------------------------------------------------------------
// Scratch (device globals; no allocation allowed)
// ---------------------------------------------------------------------------
__device__ __align__(128) float g_x0[(size_t)TV * C_IN];
__device__ __align__(128) float g_x1[(size_t)TV * H];
__device__ __align__(128) float g_h [(size_t)TV * H];
__device__ __align__(128) float g_xsr[(size_t)TV * H];
__device__ __align__(128) float g_agg[(size_t)TV * H];
__device__ __align__(128) float g_deg[(size_t)TV];
__device__ __align__(128) float g_lam[2 * HD];
__device__ __align__(128) float g_xlast[(size_t)V * H];
__device__ __align__(128) float g_xsrl [(size_t)V * H];
__device__ int g_is64;

// bf16 hi/lo split A operands for the mix GEMMs, all 8 timesteps (padded rows)
__device__ __align__(128) __nv_bfloat16 g_AmixAll_h[(size_t)T * VP * HD];
__device__ __align__(128) __nv_bfloat16 g_AmixAll_l[(size_t)T * VP * HD];

// bf16 hi/lo split, transposed weights ([N=256][K], K-major)
__device__ __align__(128) __nv_bfloat16 g_cat0_h[256 * 256], g_cat0_l[256 * 256];
__device__ __align__(128) __nv_bfloat16 g_cat1_h[256 * 512], g_cat1_l[256 * 512];
__device__ __align__(128) __nv_bfloat16 g_res0_h[256 * 128], g_res0_l[256 * 128];
__device__ __align__(128) __nv_bfloat16 g_res1_h[256 * 256], g_res1_l[256 * 256];
__device__ __align__(128) __nv_bfloat16 g_mix0_h[256 * HD],  g_mix0_l[256 * HD];
__device__ __align__(128) __nv_bfloat16 g_mix1_h[256 * HD],  g_mix1_l[256 * HD];

// ---------------------------------------------------------------------------
// Helpers
// ---------------------------------------------------------------------------
__device__ __forceinline__ uint32_t smem_u32(const void* p) {
    uint32_t a;
    asm("{ .reg .u64 t; cvta.to.shared.u64 t, %1; cvt.u32.u64 %0, t; }" : "=r"(a) : "l"(p));
    return a;
}

__device__ __forceinline__ void bf_split(float x, __nv_bfloat16& h_, __nv_bfloat16& l_) {
    h_ = __float2bfloat16(x);
    l_ = __float2bfloat16(x - __bfloat162float(h_));
}

#define LDSM_X4(r0, r1, r2, r3, addr) \
    asm volatile("ldmatrix.sync.aligned.m8n8.x4.shared.b16 {%0,%1,%2,%3}, [%4];" \
        : "=r"(r0), "=r"(r1), "=r"(r2), "=r"(r3) : "r"(addr))

#define MMA_BF16(d, a, b0, b1) \
    asm volatile("mma.sync.aligned.m16n8k16.row.col.f32.bf16.bf16.f32 " \
        "{%0,%1,%2,%3}, {%4,%5,%6,%7}, {%8,%9}, {%0,%1,%2,%3};" \
        : "+f"((d)[0]), "+f"((d)[1]), "+f"((d)[2]), "+f"((d)[3]) \
        : "r"((a)[0]), "r"((a)[1]), "r"((a)[2]), "r"((a)[3]), "r"(b0), "r"(b1))

#define CP16(dst, src) \
    asm volatile("cp.async.cg.shared.global [%0], [%1], 16;" :: "r"(dst), "l"(src))
#define CP_COMMIT() asm volatile("cp.async.commit_group;" ::: "memory")
#define CP_WAIT0()  asm volatile("cp.async.wait_group 0;" ::: "memory")

// ---------------------------------------------------------------------------
// Small kernels
// ---------------------------------------------------------------------------
__global__ void zero_kernel(float4* p, long long n4) {
    long long i = blockIdx.x * (long long)blockDim.x + threadIdx.x;
    long long stride = (long long)gridDim.x * blockDim.x;
    for (; i < n4; i += stride) p[i] = make_float4(0.f, 0.f, 0.f, 0.f);
}

__global__ void detect_kernel(const unsigned int* ei) {
    if (threadIdx.x == 0 && blockIdx.x == 0) {
        unsigned int s = 0;
        for (int i = 0; i < 64; i++) s |= ei[2 * i + 1];
        g_is64 = (s == 0) ? 1 : 0;
    }
}

__device__ __forceinline__ int load_edge(const void* ei, long long pos) {
    if (g_is64) return (int)((const long long*)ei)[pos];
    return ((const int*)ei)[pos];
}

__global__ void lam_kernel(const float* a0, const float* a1, float* lam) {
    int i = blockIdx.x * blockDim.x + threadIdx.x;
    if (i < HD)           lam[i] = expf(-expf(a0[i]));
    else if (i < 2 * HD)  lam[i] = expf(-expf(a1[i - HD]));
}

__global__ void token_mix_kernel(const float* __restrict__ xs,
                                 const float* __restrict__ w,
                                 const float* __restrict__ b,
                                 float* __restrict__ out) {
    int idx = blockIdx.x * blockDim.x + threadIdx.x;
    if (idx >= TV * C_IN) return;
    int c = idx % C_IN;
    int t = idx / (V * C_IN);
    float acc = b[c] + xs[idx] * w[c * 3 + 1];
    if (t > 0)     acc += xs[idx - V * C_IN] * w[c * 3 + 0];
    if (t < T - 1) acc += xs[idx + V * C_IN] * w[c * 3 + 2];
    out[idx] = acc;
}

__global__ void deg_kernel(const void* __restrict__ ei, float* __restrict__ deg) {
    long long i = blockIdx.x * (long long)blockDim.x + threadIdx.x;
    if (i >= (long long)T * E) return;
    int e = (int)(i % E);
    int t = (int)(i / E);
    int dst = load_edge(ei, (long long)t * 2 * E + E + e);
    atomicAdd(&deg[(long long)t * V + dst], 1.0f);
}

__global__ void scatter_kernel(const float* __restrict__ x, const void* __restrict__ ei,
                               float* __restrict__ agg, int C) {
    int chunks = C >> 2;
    long long idx = blockIdx.x * (long long)blockDim.x + threadIdx.x;
    long long total = (long long)T * E * chunks;
    if (idx >= total) return;
    int c4 = (int)(idx % chunks);
    long long te = idx / chunks;
    int e = (int)(te % E);
    int t = (int)(te / E);
    long long base = (long long)t * 2 * E;
    int src = load_edge(ei, base + e);
    int dst = load_edge(ei, base + E + e);
    float4 v = *(const float4*)&x[((long long)t * V + src) * C + c4 * 4];
    float* p = &agg[((long long)t * V + dst) * C + c4 * 4];
    asm volatile("red.global.add.v4.f32 [%0], {%1,%2,%3,%4};"
                 :: "l"(p), "f"(v.x), "f"(v.y), "f"(v.z), "f"(v.w) : "memory");
}

__global__ void mean_kernel(float* __restrict__ agg, const float* __restrict__ deg, int C) {
    int chunks = C >> 2;
    long long idx = blockIdx.x * (long long)blockDim.x + threadIdx.x;
    long long total = (long long)TV * chunks;
    if (idx >= total) return;
    long long row = idx / chunks;
    int c4 = (int)(idx % chunks);
    float inv = 1.0f / fmaxf(deg[row], 1.0f);
    float4* p = (float4*)&agg[row * C + c4 * 4];
    float4 v = *p;
    v.x *= inv; v.y *= inv; v.z *= inv; v.w *= inv;
    *p = v;
}

// Build transposed, bf16-split weights: dst[n][k] (K-major) from w1/w2 [K][256]
__global__ void bsplit_kernel(const float* __restrict__ w1, const float* __restrict__ w2,
                              int K1, int Kt,
                              __nv_bfloat16* __restrict__ hi, __nv_bfloat16* __restrict__ lo) {
    long long idx = blockIdx.x * (long long)blockDim.x + threadIdx.x;
    if (idx >= (long long)Kt * 256) return;
    int k = (int)(idx % Kt);
    int n = (int)(idx / Kt);
    float v = (k < K1) ? w1[(long long)k * 256 + n] : w2[(long long)(k - K1) * 256 + n];
    __nv_bfloat16 h_, l_;
    bf_split(v, h_, l_);
    hi[(long long)n * Kt + k] = h_;
    lo[(long long)n * Kt + k] = l_;
}

// ---------------------------------------------------------------------------
// Full SSM scan (8 steps, fp32, same op order as reference).
// ALL=true : write relu+split A for every timestep into slots t*ZST.
// ALL=false: write only the final step into slot 0.
// ---------------------------------------------------------------------------
template <bool ALL>
__global__ void scan_kernel(const float* __restrict__ h,
                            const float* __restrict__ lam,
                            const float* __restrict__ Bp,
                            __nv_bfloat16* __restrict__ Ah,
                            __nv_bfloat16* __restrict__ Al) {
    long long idx = blockIdx.x * (long long)blockDim.x + threadIdx.x;
    if (idx >= (long long)V * HD / 4) return;
    long long base = idx * 4;
    int hd = (int)(base % HD);
    long long v = base / HD;
    int hh = hd >> 4;                       // DS = 16
    float4 l = *(const float4*)&lam[hd];
    float4 b = *(const float4*)&Bp[hd];
    float4 s = make_float4(0.f, 0.f, 0.f, 0.f);
    long long vo = v * HD + hd;
#pragma unroll
    for (int t = 0; t < T; t++) {
        float x = h[((long long)t * V + v) * H + hh];
        s.x = l.x * s.x + x * b.x;
        s.y = l.y * s.y + x * b.y;
        s.z = l.z * s.z + x * b.z;
        s.w = l.w * s.w + x * b.w;
        if (ALL || t == T - 1) {
            __nv_bfloat16 h0, l0, h1, l1, h2, l2, h3, l3;
            bf_split(fmaxf(s.x, 0.f), h0, l0);
            bf_split(fmaxf(s.y, 0.f), h1, l1);
            bf_split(fmaxf(s.z, 0.f), h2, l2);
            bf_split(fmaxf(s.w, 0.f), h3, l3);
            uint2 uh, ul;
            uh.x = (uint32_t)__bfloat16_as_ushort(h0) | ((uint32_t)__bfloat16_as_ushort(h1) << 16);
            uh.y = (uint32_t)__bfloat16_as_ushort(h2) | ((uint32_t)__bfloat16_as_ushort(h3) << 16);
            ul.x = (uint32_t)__bfloat16_as_ushort(l0) | ((uint32_t)__bfloat16_as_ushort(l1) << 16);
            ul.y = (uint32_t)__bfloat16_as_ushort(l2) | ((uint32_t)__bfloat16_as_ushort(l3) << 16);
            long long off = (ALL ? (long long)t * ZST : 0) + vo;
            *(uint2*)&Ah[off] = uh;
            *(uint2*)&Al[off] = ul;
        }
    }
}

// ---------------------------------------------------------------------------
// bf16x3 mma.sync GEMM, tile 64x128, BK=32, 256 threads (8 warps 2m x 4n),
// 2 CTAs/SM, double-buffered SMEM, cp.async B (and A in MODE 2).
//   MODE 1: A = concat(A1[.,K1], A2[.,K-K1]) fp32, split in producer.
//   MODE 2: A = (Ah, Al) bf16 pre-split, z-batched by AzStride.
// C[M,256 slice n0..n0+127] = (Ah+Al) @ (Bh+Bl)^T + bias (+ Dadd)
// ---------------------------------------------------------------------------
#define ROWB 80
#define AH_T 5120            // 64 * 80
#define BH_T 10240           // 128 * 80
#define STG2 (2 * AH_T + 2 * BH_T)   // 30720
#define GS2  (2 * STG2)              // 61440

template <int MODE>
__global__ __launch_bounds__(256, 2) void mgemm2_kernel(
    const float* __restrict__ A1, const float* __restrict__ A2, int K1,
    const __nv_bfloat16* __restrict__ Ah, const __nv_bfloat16* __restrict__ Al,
    long long AzStride,
    const __nv_bfloat16* __restrict__ Bh, const __nv_bfloat16* __restrict__ Bl,
    const float* __restrict__ bias, const float* __restrict__ Dadd, long long DzStride,
    float* __restrict__ Cout, long long CzStride,
    int M, int K)
{
    extern __shared__ char smem[];
    const uint32_t sb = smem_u32(smem);
    const int tid = threadIdx.x;
    const int wid = tid >> 5;
    const int lane = tid & 31;
    const int warp_m = wid >> 2;       // 0..1
    const int warp_n = wid & 3;        // 0..3
    const int z = blockIdx.z;
    const long long m0 = (long long)blockIdx.x * 64;
    const int n0 = blockIdx.y * 128;

    const __nv_bfloat16* Ahz = Ah + (long long)z * AzStride;
    const __nv_bfloat16* Alz = Al + (long long)z * AzStride;
    const float* Dz = Dadd ? (Dadd + (long long)z * DzStride) : (const float*)0;
    float* Cz = Cout + (long long)z * CzStride;

    float acc[2][4][4];
#pragma unroll
    for (int i = 0; i < 2; i++)
#pragma unroll
        for (int j = 0; j < 4; j++)
#pragma unroll
            for (int p = 0; p < 4; p++) acc[i][j][p] = 0.f;

    const int nK = K / 32;

    // MODE 1 producer coords
    const int q = tid >> 6;            // k-octet 0..3
    const int r = tid & 63;            // row 0..63
    const long long rg1 = m0 + r;
    const bool rowok1 = (rg1 < M);
    float a8[8];

    // MODE 2 A cp.async coords
    const int arow = tid >> 2;         // 0..63
    const int akq = tid & 3;           // 0..3

    // ldmatrix base byte offsets within a stage
    const uint32_t aoff = (uint32_t)(warp_m * 32 + (lane & 15)) * ROWB +
                          (uint32_t)((lane >> 4) << 3) * 2;
    const uint32_t boff = (uint32_t)(warp_n * 32 + ((lane >> 4) << 3) + (lane & 7)) * ROWB +
                          (uint32_t)(((lane >> 3) & 1) << 3) * 2;

    auto cpB = [&](int kt, int stage) {
        const int k0 = kt * 32;
        const uint32_t base = sb + stage * STG2 + 2 * AH_T;
#pragma unroll
        for (int i = 0; i < 2; i++) {
            int idx = tid + 256 * i;   // 0..511
            int n  = idx >> 2;         // 0..127
            int kq = idx & 3;
            uint32_t dst = base + (uint32_t)n * ROWB + (uint32_t)kq * 16;
            long long soff = (long long)(n0 + n) * K + k0 + kq * 8;
            CP16(dst, Bh + soff);
            CP16(dst + BH_T, Bl + soff);
        }
    };

    auto cpA = [&](int kt, int stage) {      // MODE 2
        uint32_t dst = sb + stage * STG2 + (uint32_t)arow * ROWB + (uint32_t)akq * 16;
        long long soff = (m0 + arow) * (long long)K + kt * 32 + akq * 8;
        CP16(dst, Ahz + soff);
        CP16(dst + AH_T, Alz + soff);
    };

    auto prefA = [&](int kt) {               // MODE 1
        const int kg = kt * 32 + q * 8;
        if (rowok1) {
            const float* src = (kg < K1) ? &A1[rg1 * (long long)K1 + kg]
                                         : &A2[rg1 * (long long)(K - K1) + (kg - K1)];
            *(float4*)&a8[0] = ((const float4*)src)[0];
            *(float4*)&a8[4] = ((const float4*)src)[1];
        } else {
#pragma unroll
            for (int d = 0; d < 8; d++) a8[d] = 0.f;
        }
    };

    auto produceA = [&](int stage) {         // MODE 1
        uint32_t uh[4], ul[4];
#pragma unroll
        for (int d2 = 0; d2 < 4; d2++) {
            __nv_bfloat16 h0, l0, h1, l1;
            bf_split(a8[d2 * 2 + 0], h0, l0);
            bf_split(a8[d2 * 2 + 1], h1, l1);
            uh[d2] = (uint32_t)__bfloat16_as_ushort(h0) |
                     ((uint32_t)__bfloat16_as_ushort(h1) << 16);
            ul[d2] = (uint32_t)__bfloat16_as_ushort(l0) |
                     ((uint32_t)__bfloat16_as_ushort(l1) << 16);
        }
        const uint32_t off = (uint32_t)stage * STG2 + (uint32_t)r * ROWB + (uint32_t)q * 16;
        *(uint4*)(smem + off)        = make_uint4(uh[0], uh[1], uh[2], uh[3]);
        *(uint4*)(smem + off + AH_T) = make_uint4(ul[0], ul[1], ul[2], ul[3]);
    };

    auto compute = [&](int stage) {
        const uint32_t base = sb + stage * STG2;
#pragma unroll
        for (int ks = 0; ks < 2; ks++) {
            const uint32_t kk = (uint32_t)ks * 32;   // 16 k-elems = 32 bytes
            uint32_t a_h[2][4], a_l[2][4];
#pragma unroll
            for (int i = 0; i < 2; i++) {
                uint32_t ad = base + aoff + (uint32_t)(i * 16) * ROWB + kk;
                LDSM_X4(a_h[i][0], a_h[i][1], a_h[i][2], a_h[i][3], ad);
                LDSM_X4(a_l[i][0], a_l[i][1], a_l[i][2], a_l[i][3], ad + AH_T);
            }
            uint32_t b_h[8], b_l[8];
#pragma unroll
            for (int jj = 0; jj < 2; jj++) {
                uint32_t bd = base + 2 * AH_T + boff + (uint32_t)(jj * 16) * ROWB + kk;
                LDSM_X4(b_h[jj * 4 + 0], b_h[jj * 4 + 1], b_h[jj * 4 + 2], b_h[jj * 4 + 3], bd);
                LDSM_X4(b_l[jj * 4 + 0], b_l[jj * 4 + 1], b_l[jj * 4 + 2], b_l[jj * 4 + 3], bd + BH_T);
            }
#pragma unroll
            for (int i = 0; i < 2; i++)
#pragma unroll
                for (int j = 0; j < 4; j++) {
                    MMA_BF16(acc[i][j], a_h[i], b_h[j * 2], b_h[j * 2 + 1]);
                    MMA_BF16(acc[i][j], a_h[i], b_l[j * 2], b_l[j * 2 + 1]);
                    MMA_BF16(acc[i][j], a_l[i], b_h[j * 2], b_h[j * 2 + 1]);
                }
        }
    };

    // prologue
    if (MODE == 2) {
        cpA(0, 0);
        cpB(0, 0);
        CP_COMMIT();
    } else {
        prefA(0);
        cpB(0, 0);
        CP_COMMIT();
        produceA(0);
    }
    CP_WAIT0();
    __syncthreads();

    for (int kt = 0; kt < nK; kt++) {
        const int cur = kt & 1;
        const bool more = (kt + 1 < nK);
        if (more) {
            if (MODE == 2) {
                cpA(kt + 1, cur ^ 1);
            } else {
                prefA(kt + 1);
            }
            cpB(kt + 1, cur ^ 1);
            CP_COMMIT();
        }
        compute(cur);
        if (MODE == 1 && more) produceA(cur ^ 1);
        CP_WAIT0();
        __syncthreads();
    }

    // epilogue
#pragma unroll
    for (int i = 0; i < 2; i++) {
        long long r1 = m0 + warp_m * 32 + i * 16 + (lane >> 2);
        long long r2 = r1 + 8;
#pragma unroll
        for (int j = 0; j < 4; j++) {
            int c = n0 + warp_n * 32 + j * 8 + (lane & 3) * 2;
            float bx = 0.f, by = 0.f;
            if (bias) { float2 b2 = *(const float2*)&bias[c]; bx = b2.x; by = b2.y; }
            if (r1 < M) {
                float vx = acc[i][j][0] + bx, vy = acc[i][j][1] + by;
                if (Dz) { float2 d = *(const float2*)&Dz[r1 * 256 + c]; vx += d.x; vy += d.y; }
                *(float2*)&Cz[r1 * 256 + c] = make_float2(vx, vy);
            }
            if (r2 < M) {
                float vx = acc[i][j][2] + bx, vy = acc[i][j][3] + by;
                if (Dz) { float2 d = *(const float2*)&Dz[r2 * 256 + c]; vx += d.x; vy += d.y; }
                *(float2*)&Cz[r2 * 256 + c] = make_float2(vx, vy);
            }
        }
    }
}

// ---------------------------------------------------------------------------
// fp32 SGEMM for the small output head (N=64)
// ---------------------------------------------------------------------------
#define BMH 128
#define BNH 128
#define BKH 8

__global__ __launch_bounds__(256) void sgemm_kernel(
    const float* __restrict__ A, const float* __restrict__ B,
    const float* __restrict__ bias, float* __restrict__ C, int M, int N, int K)
{
    __shared__ float As[BKH][BMH];
    __shared__ float Bs[BKH][BNH];
    int row0 = blockIdx.y * BMH;
    int col0 = blockIdx.x * BNH;
    int tid = threadIdx.x;
    int aRow = tid >> 1;
    int aCol = (tid & 1) * 4;
    int bRow = tid >> 5;
    int bCol = (tid & 31) * 4;
    int tx = tid & 15;
    int ty = tid >> 4;
    float acc[8][8];
#pragma unroll
    for (int i = 0; i < 8; i++)
#pragma unroll
        for (int j = 0; j < 8; j++) acc[i][j] = 0.f;
    int nK = K / BKH;
    for (int kt = 0; kt < nK; ++kt) {
        int k0 = kt * BKH;
        float4 av = make_float4(0.f, 0.f, 0.f, 0.f);
        int gr = row0 + aRow;
        if (gr < M) av = *(const float4*)&A[(long long)gr * K + k0 + aCol];
        As[aCol + 0][aRow] = av.x;
        As[aCol + 1][aRow] = av.y;
        As[aCol + 2][aRow] = av.z;
        As[aCol + 3][aRow] = av.w;
        float4 bv = make_float4(0.f, 0.f, 0.f, 0.f);
        int gc = col0 + bCol;
        if (gc < N) bv = *(const float4*)&B[(long long)(k0 + bRow) * N + gc];
        *(float4*)&Bs[bRow][bCol] = bv;
        __syncthreads();
#pragma unroll
        for (int k = 0; k < BKH; k++) {
            float ar[8], br[8];
#pragma unroll
            for (int i = 0; i < 8; i++) ar[i] = As[k][ty * 8 + i];
#pragma unroll
            for (int j = 0; j < 8; j++) br[j] = Bs[k][tx * 8 + j];
#pragma unroll
            for (int i = 0; i < 8; i++)
#pragma unroll
                for (int j = 0; j < 8; j++) acc[i][j] += ar[i] * br[j];
        }
        __syncthreads();
    }
#pragma unroll
    for (int i = 0; i < 8; i++) {
        int r = row0 + ty * 8 + i;
        if (r >= M) continue;
#pragma unroll
        for (int j = 0; j < 8; j++) {
            int c = col0 + tx * 8 + j;
            if (c >= N) continue;
            C[(long long)r * N + c] = acc[i][j] + bias[c];
        }
    }
}

// ---------------------------------------------------------------------------
// Host helpers
// ---------------------------------------------------------------------------
static void zero_buf(float* p, long long n_floats) {
    zero_kernel<<<1024, 256>>>((float4*)p, n_floats / 4);
}

// MODE 1: C = concat(A1,A2) @ W + bias
static void gemm_cat(const float* A1, const float* A2, int K1,
                     const __nv_bfloat16* Bh, const __nv_bfloat16* Bl,
                     const float* bias, float* C, int M, int K) {
    dim3 grid((M + 63) / 64, 2, 1);
    mgemm2_kernel<1><<<grid, 256, GS2>>>(A1, A2, K1, nullptr, nullptr, 0,
                                         Bh, Bl, bias, nullptr, 0, C, 0, M, K);
}

// MODE 2: C[z] = (Ah+Al)[z] @ W + bias + D[z], z-batched
static void gemm_bf(const __nv_bfloat16* Ah, const __nv_bfloat16* Al, long long AzS,
                    const __nv_bfloat16* Bh, const __nv_bfloat16* Bl,
                    const float* bias, const float* Dadd, long long DzS,
                    float* C, long long CzS, int M, int K, int nz) {
    dim3 grid((M + 63) / 64, 2, nz);
    mgemm2_kernel<2><<<grid, 256, GS2>>>(nullptr, nullptr, 0, Ah, Al, AzS,
                                         Bh, Bl, bias, Dadd, DzS, C, CzS, M, K);
}

// ---------------------------------------------------------------------------
// Launch
// ---------------------------------------------------------------------------
extern "C" void kernel_launch(void* const* d_in, const int* in_sizes, int n_in,
                              void* d_out, int out_size) {
    const float* xs      = (const float*)d_in[0];
    const void*  ei      = d_in[1];
    const float* w_pre   = (const float*)d_in[2];
    const float* b_pre   = (const float*)d_in[3];

    const float* w_res0  = (const float*)d_in[4];
    const float* b_res0  = (const float*)d_in[5];
    const float* w_self0 = (const float*)d_in[6];
    const float* w_neigh0= (const float*)d_in[7];
    const float* b_sage0 = (const float*)d_in[8];
    const float* a_log0  = (const float*)d_in[9];
    const float* B0      = (const float*)d_in[10];
    const float* w_mix0  = (const float*)d_in[11];
    const float* b_mix0  = (const float*)d_in[12];

    const float* w_res1  = (const float*)d_in[13];
    const float* b_res1  = (const float*)d_in[14];
    const float* w_self1 = (const float*)d_in[15];
    const float* w_neigh1= (const float*)d_in[16];
    const float* b_sage1 = (const float*)d_in[17];
    const float* a_log1  = (const float*)d_in[18];
    const float* B1      = (const float*)d_in[19];
    const float* w_mix1  = (const float*)d_in[20];
    const float* b_mix1  = (const float*)d_in[21];

    const float* w_out   = (const float*)d_in[22];
    const float* b_out   = (const float*)d_in[23];

    float *x0, *x1, *h, *xsr, *agg, *deg, *lam, *xlast, *xsrl;
    cudaGetSymbolAddress((void**)&x0,    g_x0);
    cudaGetSymbolAddress((void**)&x1,    g_x1);
    cudaGetSymbolAddress((void**)&h,     g_h);
    cudaGetSymbolAddress((void**)&xsr,   g_xsr);
    cudaGetSymbolAddress((void**)&agg,   g_agg);
    cudaGetSymbolAddress((void**)&deg,   g_deg);
    cudaGetSymbolAddress((void**)&lam,   g_lam);
    cudaGetSymbolAddress((void**)&xlast, g_xlast);
    cudaGetSymbolAddress((void**)&xsrl,  g_xsrl);

    __nv_bfloat16 *AmixH, *AmixL;
    __nv_bfloat16 *cat0h, *cat0l, *cat1h, *cat1l, *res0h, *res0l, *res1h, *res1l;
    __nv_bfloat16 *mix0h, *mix0l, *mix1h, *mix1l;
    cudaGetSymbolAddress((void**)&AmixH, g_AmixAll_h);
    cudaGetSymbolAddress((void**)&AmixL, g_AmixAll_l);
    cudaGetSymbolAddress((void**)&cat0h, g_cat0_h);
    cudaGetSymbolAddress((void**)&cat0l, g_cat0_l);
    cudaGetSymbolAddress((void**)&cat1h, g_cat1_h);
    cudaGetSymbolAddress((void**)&cat1l, g_cat1_l);
    cudaGetSymbolAddress((void**)&res0h, g_res0_h);
    cudaGetSymbolAddress((void**)&res0l, g_res0_l);
    cudaGetSymbolAddress((void**)&res1h, g_res1_h);
    cudaGetSymbolAddress((void**)&res1l, g_res1_l);
    cudaGetSymbolAddress((void**)&mix0h, g_mix0_h);
    cudaGetSymbolAddress((void**)&mix0l, g_mix0_l);
    cudaGetSymbolAddress((void**)&mix1h, g_mix1_h);
    cudaGetSymbolAddress((void**)&mix1l, g_mix1_l);

    cudaFuncSetAttribute(mgemm2_kernel<1>,
                         cudaFuncAttributeMaxDynamicSharedMemorySize, GS2);
    cudaFuncSetAttribute(mgemm2_kernel<2>,
                         cudaFuncAttributeMaxDynamicSharedMemorySize, GS2);

    detect_kernel<<<1, 32>>>((const unsigned int*)ei);
    lam_kernel<<<(2 * HD + 255) / 256, 256>>>(a_log0, a_log1, lam);
    token_mix_kernel<<<(TV * C_IN + 255) / 256, 256>>>(xs, w_pre, b_pre, x0);

    // weight preprocessing (transpose + bf16 hi/lo split)
    {
        auto bs = [](const float* w1, const float* w2, int K1, int Kt,
                     __nv_bfloat16* hi, __nv_bfloat16* lo) {
            long long tot = (long long)Kt * 256;
            bsplit_kernel<<<(int)((tot + 255) / 256), 256>>>(w1, w2, K1, Kt, hi, lo);
        };
        bs(w_self0, w_neigh0, C_IN, 2 * C_IN, cat0h, cat0l);
        bs(w_self1, w_neigh1, H, 2 * H, cat1h, cat1l);
        bs(w_res0, nullptr, C_IN, C_IN, res0h, res0l);
        bs(w_res1, nullptr, H, H, res1h, res1l);
        bs(w_mix0, nullptr, HD, HD, mix0h, mix0l);
        bs(w_mix1, nullptr, HD, HD, mix1h, mix1l);
    }

    // degrees (shared by both layers)
    zero_buf(deg, (long long)TV);
    deg_kernel<<<(int)(((long long)T * E + 255) / 256), 256>>>(ei, deg);

    const long long VHD4 = (long long)V * HD / 4;

    // ---------------- layer 0 ----------------
    zero_buf(agg, (long long)TV * C_IN);
    {
        long long tot = (long long)T * E * (C_IN / 4);
        scatter_kernel<<<(int)((tot + 255) / 256), 256>>>(x0, ei, agg, C_IN);
        long long tm = (long long)TV * (C_IN / 4);
        mean_kernel<<<(int)((tm + 255) / 256), 256>>>(agg, deg, C_IN);
    }
    gemm_cat(x0, agg, C_IN, cat0h, cat0l, b_sage0, h,   TV, 2 * C_IN);   // sage0
    gemm_cat(x0, x0,  C_IN, res0h, res0l, b_res0,  xsr, TV, C_IN);       // res0

    // full fp32 scan, split A for all 8 timesteps in one pass
    scan_kernel<true><<<(int)((VHD4 + 255) / 256), 256>>>(h, lam, B0, AmixH, AmixL);

    // all 8 mix0 GEMMs in one batched launch (z = t)
    gemm_bf(AmixH, AmixL, ZST, mix0h, mix0l, b_mix0,
            xsr, (long long)V * H, x1, (long long)V * H, V, HD, T);

    // ---------------- layer 1 ----------------
    zero_buf(agg, (long long)TV * H);
    {
        long long tot = (long long)T * E * (H / 4);
        scatter_kernel<<<(int)((tot + 255) / 256), 256>>>(x1, ei, agg, H);
        long long tm = (long long)TV * (H / 4);
        mean_kernel<<<(int)((tm + 255) / 256), 256>>>(agg, deg, H);
    }
    gemm_cat(x1, agg, H, cat1h, cat1l, b_sage1, h, TV, 2 * H);           // sage1
    gemm_cat(x1 + (long long)(T - 1) * V * H, x1 + (long long)(T - 1) * V * H, H,
             res1h, res1l, b_res1, xsrl, V, H);                          // res1 (t=7)

    // layer-1 scan: only final step needed
    scan_kernel<false><<<(int)((VHD4 + 255) / 256), 256>>>(h, lam + HD, B1, AmixH, AmixL);
    gemm_bf(AmixH, AmixL, 0, mix1h, mix1l, b_mix1,
            xsrl, 0, xlast, 0, V, HD, 1);                                // mix1

    // ---------------- output head ----------------
    dim3 og((C_OUT + BNH - 1) / BNH, (V + BMH - 1) / BMH);
    sgemm_kernel<<<og, 256>>>(xlast, w_out, b_out, (float*)d_out, V, C_OUT, H);
}